// round 1
// baseline (speedup 1.0000x reference)
#include <cuda_runtime.h>
#include <math.h>

#define MAXN 16384
#define MAXE 524288
#define NTAB 4096
#define RMAXF 5.0f
#define NLAYERS 3

// ---------------- static scratch (no allocation allowed) ----------------
__device__ float4 g_ev[MAXE];        // unsorted per-edge {y1.x,y1.y,y1.z,r}
__device__ float4 g_rec[MAXE];       // dst-sorted records
__device__ int    g_srcs[MAXE];      // dst-sorted src index
__device__ int    g_hist[MAXN];
__device__ int    g_cur[MAXN];
__device__ int    g_off[MAXN + 1];
__device__ float  g_wtab[NLAYERS * NTAB * 320];  // radial path-weight table
__device__ float  g_s[MAXN * 64];
__device__ float  g_v[MAXN * 192];   // layout [n][3][64]
__device__ float  g_as[MAXN * 64];
__device__ float  g_av[MAXN * 192];

// ---------------- init: s = w_lin_in[type], v = 0, hist = 0 ----------------
__global__ void k_init(const int* __restrict__ atom_type,
                       const float* __restrict__ w_lin_in, int N) {
    int i = blockIdx.x * blockDim.x + threadIdx.x;
    if (i < N * 192) g_v[i] = 0.f;
    if (i < N * 64) {
        int n = i >> 6, c = i & 63;
        g_s[i] = w_lin_in[atom_type[n] * 64 + c];
    }
    if (i < N) g_hist[i] = 0;
}

// ---------------- edge preprocess: vec, r, y1; histogram dst ----------------
__global__ void k_edge_pre(const float* __restrict__ pos,
                           const int* __restrict__ esrc,
                           const int* __restrict__ edst,
                           const float* __restrict__ shift,
                           const float* __restrict__ cell,
                           const int* __restrict__ img, int E) {
    int e = blockIdx.x * blockDim.x + threadIdx.x;
    if (e >= E) return;
    int s = esrc[e], d = edst[e];
    float vx = pos[d * 3 + 0] - pos[s * 3 + 0];
    float vy = pos[d * 3 + 1] - pos[s * 3 + 1];
    float vz = pos[d * 3 + 2] - pos[s * 3 + 2];
    float s0 = shift[e * 3 + 0], s1 = shift[e * 3 + 1], s2 = shift[e * 3 + 2];
    const float* Cm = cell + img[s] * 9;
    vx += s0 * Cm[0] + s1 * Cm[3] + s2 * Cm[6];
    vy += s0 * Cm[1] + s1 * Cm[4] + s2 * Cm[7];
    vz += s0 * Cm[2] + s1 * Cm[5] + s2 * Cm[8];
    float r = sqrtf(vx * vx + vy * vy + vz * vz);
    float inv = 1.7320508075688772f / fmaxf(r, 1e-9f);  // sqrt3 * unit
    g_ev[e] = make_float4(vx * inv, vy * inv, vz * inv, r);
    atomicAdd(&g_hist[d], 1);
}

// ---------------- single-block exclusive scan of hist ----------------
__global__ void k_scan(int N) {
    __shared__ int sm[1024];
    int tid = threadIdx.x;
    int per = (N + 1023) >> 10;
    int st = tid * per;
    int s = 0;
    for (int i = 0; i < per; i++) { int idx = st + i; if (idx < N) s += g_hist[idx]; }
    sm[tid] = s;
    __syncthreads();
    for (int d = 1; d < 1024; d <<= 1) {
        int v = (tid >= d) ? sm[tid - d] : 0;
        __syncthreads();
        sm[tid] += v;
        __syncthreads();
    }
    int pre = tid ? sm[tid - 1] : 0;
    for (int i = 0; i < per; i++) {
        int idx = st + i;
        if (idx < N) { g_off[idx] = pre; g_cur[idx] = pre; pre += g_hist[idx]; }
    }
    if (tid == 0) g_off[N] = sm[1023];
}

// ---------------- scatter edges into dst-sorted order ----------------
__global__ void k_scatter(const int* __restrict__ esrc,
                          const int* __restrict__ edst, int E) {
    int e = blockIdx.x * blockDim.x + threadIdx.x;
    if (e >= E) return;
    int d = edst[e];
    int p = atomicAdd(&g_cur[d], 1);
    g_rec[p] = g_ev[e];
    g_srcs[p] = esrc[e];
}

// ---------------- build radial path-weight table ----------------
// w(r) = silu(emb(r)@W1+b1)@W2, with 1/sqrt(AVG_DEG) baked in,
// extra 1/sqrt3 on path2 and 1/sqrt2 on path5.
__global__ void k_table(const float* __restrict__ mw1,
                        const float* __restrict__ mb1,
                        const float* __restrict__ mw2) {
    int L = blockIdx.x / NTAB;
    int entry = blockIdx.x % NTAB;
    int t = threadIdx.x;  // 0..63
    float r = (float)entry * (RMAXF / (float)(NTAB - 1));
    float rs = fmaxf(r, 1e-9f);
    float x = r / RMAXF;
    float x2 = x * x;
    float x6 = x2 * x2 * x2;
    float fc = 1.f - 28.f * x6 + 48.f * x6 * x - 21.f * x6 * x2;
    if (x >= 1.f) fc = 0.f;
    float cscale = sqrtf(2.f / RMAXF) * fc / rs;
    float arg = 3.14159265358979323846f * rs / RMAXF;
    float emb[8];
#pragma unroll
    for (int n = 0; n < 8; n++) emb[n] = cscale * sinf((float)(n + 1) * arg);

    float h = mb1[L * 64 + t];
#pragma unroll
    for (int j = 0; j < 8; j++) h += emb[j] * mw1[(L * 8 + j) * 64 + t];
    h = h / (1.f + expf(-h));  // silu

    __shared__ float sh[64];
    sh[t] = h;
    __syncthreads();

    float acc[5] = {0.f, 0.f, 0.f, 0.f, 0.f};
    for (int j = 0; j < 64; j++) {
        float hj = sh[j];
        const float* row = mw2 + (size_t)(L * 64 + j) * 320;
#pragma unroll
        for (int k = 0; k < 5; k++) acc[k] += hj * row[k * 64 + t];
    }
    const float ISD = 0.17677669529663687f;          // 1/sqrt(32)
    const float SC[5] = {ISD, ISD * 0.57735026918962576f, ISD, ISD,
                         ISD * 0.70710678118654752f};
    float* out = g_wtab + ((size_t)L * NTAB + entry) * 320;
#pragma unroll
    for (int k = 0; k < 5; k++) out[k * 64 + t] = acc[k] * SC[k];
}

// ---------------- main per-layer aggregate (warp per dst atom) ----------------
__global__ void k_aggregate(int L, int N) {
    int gw = (blockIdx.x * blockDim.x + threadIdx.x) >> 5;
    if (gw >= N) return;
    int lane = threadIdx.x & 31;
    int c0 = lane << 1;
    int o0 = g_off[gw], o1 = g_off[gw + 1];
    float aS0 = 0, aS1 = 0, aX0 = 0, aX1 = 0, aY0 = 0, aY1 = 0, aZ0 = 0, aZ1 = 0;
    const float* tab = g_wtab + (size_t)L * NTAB * 320;
    for (int p = o0; p < o1; ++p) {
        float4 rec = g_rec[p];
        float r = rec.w;
        if (r >= RMAXF) continue;  // fc=0 -> all path weights 0
        int src = g_srcs[p];
        float tt = r * ((float)(NTAB - 1) / RMAXF);
        int i0 = (int)tt;
        if (i0 > NTAB - 2) i0 = NTAB - 2;
        float f = tt - (float)i0;
        const float* row = tab + i0 * 320 + c0;
        float2 l0 = *(const float2*)(row);
        float2 h0 = *(const float2*)(row + 320);
        float2 l1 = *(const float2*)(row + 64);
        float2 h1 = *(const float2*)(row + 384);
        float2 l2 = *(const float2*)(row + 128);
        float2 h2 = *(const float2*)(row + 448);
        float2 l3 = *(const float2*)(row + 192);
        float2 h3 = *(const float2*)(row + 512);
        float2 l4 = *(const float2*)(row + 256);
        float2 h4 = *(const float2*)(row + 576);
        float w1a = fmaf(f, h0.x - l0.x, l0.x), w1b = fmaf(f, h0.y - l0.y, l0.y);
        float w2a = fmaf(f, h1.x - l1.x, l1.x), w2b = fmaf(f, h1.y - l1.y, l1.y);
        float w3a = fmaf(f, h2.x - l2.x, l2.x), w3b = fmaf(f, h2.y - l2.y, l2.y);
        float w4a = fmaf(f, h3.x - l3.x, l3.x), w4b = fmaf(f, h3.y - l3.y, l3.y);
        float w5a = fmaf(f, h4.x - l4.x, l4.x), w5b = fmaf(f, h4.y - l4.y, l4.y);

        float2 s01 = *(const float2*)(g_s + src * 64 + c0);
        const float* vp = g_v + src * 192 + c0;
        float2 vx = *(const float2*)(vp);
        float2 vy = *(const float2*)(vp + 64);
        float2 vz = *(const float2*)(vp + 128);
        float yx = rec.x, yy = rec.y, yz = rec.z;

        float vd0 = vx.x * yx + vy.x * yy + vz.x * yz;
        float vd1 = vx.y * yx + vy.y * yy + vz.y * yz;
        aS0 += w1a * s01.x + w2a * vd0;
        aS1 += w1b * s01.y + w2b * vd1;
        float t3a = w3a * s01.x, t3b = w3b * s01.y;
        aX0 += t3a * yx + w4a * vx.x + w5a * (vy.x * yz - vz.x * yy);
        aY0 += t3a * yy + w4a * vy.x + w5a * (vz.x * yx - vx.x * yz);
        aZ0 += t3a * yz + w4a * vz.x + w5a * (vx.x * yy - vy.x * yx);
        aX1 += t3b * yx + w4b * vx.y + w5b * (vy.y * yz - vz.y * yy);
        aY1 += t3b * yy + w4b * vy.y + w5b * (vz.y * yx - vx.y * yz);
        aZ1 += t3b * yz + w4b * vz.y + w5b * (vx.y * yy - vy.y * yx);
    }
    *(float2*)(g_as + gw * 64 + c0) = make_float2(aS0, aS1);
    float* ov = g_av + gw * 192 + c0;
    *(float2*)(ov) = make_float2(aX0, aX1);
    *(float2*)(ov + 64) = make_float2(aY0, aY1);
    *(float2*)(ov + 128) = make_float2(aZ0, aZ1);
}

// ---------------- node self-interaction + resnet ----------------
__global__ void k_node(int L, int N, const float* __restrict__ wss,
                       const float* __restrict__ wsv,
                       const float* __restrict__ wgt) {
    __shared__ float sWs[4096];
    __shared__ float sWv[4096];
    __shared__ float sWg[4096];
    const float* ps = wss + (size_t)L * 4096;
    const float* pv = wsv + (size_t)L * 4096;
    const float* pg = wgt + (size_t)L * 4096;
    for (int i = threadIdx.x; i < 4096; i += blockDim.x) {
        sWs[i] = ps[i]; sWv[i] = pv[i]; sWg[i] = pg[i];
    }
    __syncthreads();
    int gw = blockIdx.x * 8 + (threadIdx.x >> 5);
    if (gw >= N) return;
    int lane = threadIdx.x & 31;
    int c0 = lane << 1;
    float2 a = *(const float2*)(g_as + gw * 64 + c0);
    const float* avp = g_av + gw * 192 + c0;
    float2 ax = *(const float2*)(avp);
    float2 ay = *(const float2*)(avp + 64);
    float2 az = *(const float2*)(avp + 128);
    float gs0 = 0, gs1 = 0, t0 = 0, t1 = 0;
    float vx0 = 0, vx1 = 0, vy0 = 0, vy1 = 0, vz0 = 0, vz1 = 0;
#pragma unroll
    for (int j = 0; j < 64; j++) {
        int sl = j >> 1;
        float aj = __shfl_sync(0xffffffffu, (j & 1) ? a.y : a.x, sl);
        float jx = __shfl_sync(0xffffffffu, (j & 1) ? ax.y : ax.x, sl);
        float jy = __shfl_sync(0xffffffffu, (j & 1) ? ay.y : ay.x, sl);
        float jz = __shfl_sync(0xffffffffu, (j & 1) ? az.y : az.x, sl);
        float2 wg2 = *(const float2*)(sWg + j * 64 + c0);
        float2 ws2 = *(const float2*)(sWs + j * 64 + c0);
        float2 wv2 = *(const float2*)(sWv + j * 64 + c0);
        gs0 += aj * wg2.x; gs1 += aj * wg2.y;
        t0 += aj * ws2.x;  t1 += aj * ws2.y;
        vx0 += jx * wv2.x; vx1 += jx * wv2.y;
        vy0 += jy * wv2.x; vy1 += jy * wv2.y;
        vz0 += jz * wv2.x; vz1 += jz * wv2.y;
    }
    float g0 = 1.f / (1.f + expf(-gs0));
    float g1 = 1.f / (1.f + expf(-gs1));
    float si0 = t0 / (1.f + expf(-t0));
    float si1 = t1 / (1.f + expf(-t1));
    float* sp = g_s + gw * 64 + c0;
    float2 sv = *(float2*)sp;
    sv.x += si0; sv.y += si1;
    *(float2*)sp = sv;
    float* vp = g_v + gw * 192 + c0;
    float2 vv;
    vv = *(float2*)(vp);       vv.x += vx0 * g0; vv.y += vx1 * g1; *(float2*)(vp) = vv;
    vv = *(float2*)(vp + 64);  vv.x += vy0 * g0; vv.y += vy1 * g1; *(float2*)(vp + 64) = vv;
    vv = *(float2*)(vp + 128); vv.x += vz0 * g0; vv.y += vz1 * g1; *(float2*)(vp + 128) = vv;
}

// ---------------- final energy head: (s @ w_lin1) @ w_lin2 ----------------
__global__ void k_energy(int N, const float* __restrict__ wl1,
                         const float* __restrict__ wl2,
                         float* __restrict__ out) {
    __shared__ float sW[1024];
    __shared__ float sw2[16];
    for (int i = threadIdx.x; i < 1024; i += blockDim.x) sW[i] = wl1[i];
    if (threadIdx.x < 16) sw2[threadIdx.x] = wl2[threadIdx.x];
    __syncthreads();
    int gw = blockIdx.x * 8 + (threadIdx.x >> 5);
    if (gw >= N) return;
    int lane = threadIdx.x & 31;
    int c0 = lane << 1;
    float2 s = *(const float2*)(g_s + gw * 64 + c0);
    float p[16];
#pragma unroll
    for (int k = 0; k < 16; k++)
        p[k] = s.x * sW[c0 * 16 + k] + s.y * sW[(c0 + 1) * 16 + k];
#pragma unroll
    for (int d = 16; d >= 1; d >>= 1) {
#pragma unroll
        for (int k = 0; k < 16; k++) p[k] += __shfl_down_sync(0xffffffffu, p[k], d);
    }
    if (lane == 0) {
        float e = 0.f;
#pragma unroll
        for (int k = 0; k < 16; k++) e += p[k] * sw2[k];
        out[gw] = e;
    }
}

// ---------------- launch ----------------
extern "C" void kernel_launch(void* const* d_in, const int* in_sizes, int n_in,
                              void* d_out, int out_size) {
    const int*   atom_type = (const int*)d_in[0];
    const float* atom_pos  = (const float*)d_in[1];
    const int*   edge_src  = (const int*)d_in[2];
    const int*   edge_dst  = (const int*)d_in[3];
    const float* shift     = (const float*)d_in[4];
    const float* cell      = (const float*)d_in[5];
    const int*   image_idx = (const int*)d_in[6];
    const float* w_lin_in  = (const float*)d_in[7];
    const float* mw1       = (const float*)d_in[8];
    const float* mb1       = (const float*)d_in[9];
    const float* mw2       = (const float*)d_in[10];
    const float* wss       = (const float*)d_in[11];
    const float* wsv       = (const float*)d_in[12];
    const float* wgt       = (const float*)d_in[13];
    const float* wl1       = (const float*)d_in[14];
    const float* wl2       = (const float*)d_in[15];
    int N = in_sizes[0];
    int E = in_sizes[2];
    float* out = (float*)d_out;

    k_init<<<(N * 192 + 255) / 256, 256>>>(atom_type, w_lin_in, N);
    k_edge_pre<<<(E + 255) / 256, 256>>>(atom_pos, edge_src, edge_dst, shift,
                                         cell, image_idx, E);
    k_scan<<<1, 1024>>>(N);
    k_scatter<<<(E + 255) / 256, 256>>>(edge_src, edge_dst, E);
    k_table<<<NLAYERS * NTAB, 64>>>(mw1, mb1, mw2);
    for (int L = 0; L < NLAYERS; ++L) {
        k_aggregate<<<(N * 32 + 255) / 256, 256>>>(L, N);
        k_node<<<(N + 7) / 8, 256>>>(L, N, wss, wsv, wgt);
    }
    k_energy<<<(N + 7) / 8, 256>>>(N, wl1, wl2, out);
}

// round 2
// speedup vs baseline: 1.0392x; 1.0392x over previous
#include <cuda_runtime.h>
#include <cuda_fp16.h>
#include <math.h>

#define MAXN 16384
#define MAXE 524288
#define NTAB 4096
#define RMAXF 5.0f
#define NLAYERS 3

// ---------------- static scratch (no allocation allowed) ----------------
__device__ float4  g_ev[MAXE];        // unsorted per-edge {y1.x,y1.y,y1.z,r}
__device__ float4  g_rec[MAXE];       // dst-sorted records
__device__ int     g_srcs[MAXE];      // dst-sorted src index
__device__ int     g_hist[MAXN];
__device__ int     g_cur[MAXN];
__device__ int     g_off[MAXN + 1];
__device__ float   g_wtab[NLAYERS * NTAB * 320];    // fp32 staging table
__device__ __half2 g_wtabh[NLAYERS * NTAB * 320];   // packed (val, delta) table
__device__ float   g_s[MAXN * 64];
__device__ float   g_v[MAXN * 192];   // layout [n][3][64]
__device__ float   g_as[MAXN * 64];
__device__ float   g_av[MAXN * 192];

// ---------------- init: s = w_lin_in[type], v = 0, hist = 0 ----------------
__global__ void k_init(const int* __restrict__ atom_type,
                       const float* __restrict__ w_lin_in, int N) {
    int i = blockIdx.x * blockDim.x + threadIdx.x;
    if (i < N * 192) g_v[i] = 0.f;
    if (i < N * 64) {
        int n = i >> 6, c = i & 63;
        g_s[i] = w_lin_in[atom_type[n] * 64 + c];
    }
    if (i < N) g_hist[i] = 0;
}

// ---------------- edge preprocess: vec, r, y1; histogram dst ----------------
__global__ void k_edge_pre(const float* __restrict__ pos,
                           const int* __restrict__ esrc,
                           const int* __restrict__ edst,
                           const float* __restrict__ shift,
                           const float* __restrict__ cell,
                           const int* __restrict__ img, int E) {
    int e = blockIdx.x * blockDim.x + threadIdx.x;
    if (e >= E) return;
    int s = esrc[e], d = edst[e];
    float vx = pos[d * 3 + 0] - pos[s * 3 + 0];
    float vy = pos[d * 3 + 1] - pos[s * 3 + 1];
    float vz = pos[d * 3 + 2] - pos[s * 3 + 2];
    float s0 = shift[e * 3 + 0], s1 = shift[e * 3 + 1], s2 = shift[e * 3 + 2];
    const float* Cm = cell + img[s] * 9;
    vx += s0 * Cm[0] + s1 * Cm[3] + s2 * Cm[6];
    vy += s0 * Cm[1] + s1 * Cm[4] + s2 * Cm[7];
    vz += s0 * Cm[2] + s1 * Cm[5] + s2 * Cm[8];
    float r = sqrtf(vx * vx + vy * vy + vz * vz);
    float inv = 1.7320508075688772f / fmaxf(r, 1e-9f);  // sqrt3 * unit
    g_ev[e] = make_float4(vx * inv, vy * inv, vz * inv, r);
    atomicAdd(&g_hist[d], 1);
}

// ---------------- single-block exclusive scan of hist ----------------
__global__ void k_scan(int N) {
    __shared__ int sm[1024];
    int tid = threadIdx.x;
    int per = (N + 1023) >> 10;
    int st = tid * per;
    int s = 0;
    for (int i = 0; i < per; i++) { int idx = st + i; if (idx < N) s += g_hist[idx]; }
    sm[tid] = s;
    __syncthreads();
    for (int d = 1; d < 1024; d <<= 1) {
        int v = (tid >= d) ? sm[tid - d] : 0;
        __syncthreads();
        sm[tid] += v;
        __syncthreads();
    }
    int pre = tid ? sm[tid - 1] : 0;
    for (int i = 0; i < per; i++) {
        int idx = st + i;
        if (idx < N) { g_off[idx] = pre; g_cur[idx] = pre; pre += g_hist[idx]; }
    }
    if (tid == 0) g_off[N] = sm[1023];
}

// ---------------- scatter edges into dst-sorted order ----------------
__global__ void k_scatter(const int* __restrict__ esrc,
                          const int* __restrict__ edst, int E) {
    int e = blockIdx.x * blockDim.x + threadIdx.x;
    if (e >= E) return;
    int d = edst[e];
    int p = atomicAdd(&g_cur[d], 1);
    g_rec[p] = g_ev[e];
    g_srcs[p] = esrc[e];
}

// ---------------- build radial path-weight table (fp32 staging) ----------------
__global__ void k_table(const float* __restrict__ mw1,
                        const float* __restrict__ mb1,
                        const float* __restrict__ mw2) {
    int L = blockIdx.x / NTAB;
    int entry = blockIdx.x % NTAB;
    int t = threadIdx.x;  // 0..63
    float r = (float)entry * (RMAXF / (float)(NTAB - 1));
    float rs = fmaxf(r, 1e-9f);
    float x = r / RMAXF;
    float x2 = x * x;
    float x6 = x2 * x2 * x2;
    float fc = 1.f - 28.f * x6 + 48.f * x6 * x - 21.f * x6 * x2;
    if (x >= 1.f) fc = 0.f;
    float cscale = sqrtf(2.f / RMAXF) * fc / rs;
    float arg = 3.14159265358979323846f * rs / RMAXF;
    float emb[8];
#pragma unroll
    for (int n = 0; n < 8; n++) emb[n] = cscale * sinf((float)(n + 1) * arg);

    float h = mb1[L * 64 + t];
#pragma unroll
    for (int j = 0; j < 8; j++) h += emb[j] * mw1[(L * 8 + j) * 64 + t];
    h = h / (1.f + expf(-h));  // silu

    __shared__ float sh[64];
    sh[t] = h;
    __syncthreads();

    float acc[5] = {0.f, 0.f, 0.f, 0.f, 0.f};
    for (int j = 0; j < 64; j++) {
        float hj = sh[j];
        const float* row = mw2 + (size_t)(L * 64 + j) * 320;
#pragma unroll
        for (int k = 0; k < 5; k++) acc[k] += hj * row[k * 64 + t];
    }
    const float ISD = 0.17677669529663687f;          // 1/sqrt(32)
    const float SC[5] = {ISD, ISD * 0.57735026918962576f, ISD, ISD,
                         ISD * 0.70710678118654752f};
    float* out = g_wtab + ((size_t)L * NTAB + entry) * 320;
#pragma unroll
    for (int k = 0; k < 5; k++) out[k * 64 + t] = acc[k] * SC[k];
}

// ---------------- pack fp32 table into half2 (val, delta) ----------------
__global__ void k_pack() {
    int L = blockIdx.x / NTAB;
    int entry = blockIdx.x % NTAB;
    int t = threadIdx.x;  // 0..63
    const float* cur = g_wtab + ((size_t)L * NTAB + entry) * 320;
    const float* nxt = cur + (entry < NTAB - 1 ? 320 : 0);
    __half2* out = g_wtabh + ((size_t)L * NTAB + entry) * 320;
#pragma unroll
    for (int k = 0; k < 5; k++) {
        float v = cur[k * 64 + t];
        float d = nxt[k * 64 + t] - v;
        out[k * 64 + t] = __floats2half2_rn(v, d);
    }
}

__device__ __forceinline__ void lerp2(uint2 q, float f, float& wa, float& wb) {
    float2 a = __half22float2(*(__half2*)&q.x);  // (val_a, delta_a)
    float2 b = __half22float2(*(__half2*)&q.y);  // (val_b, delta_b)
    wa = fmaf(f, a.y, a.x);
    wb = fmaf(f, b.y, b.x);
}

// ---------------- main per-layer aggregate (warp per dst atom) ----------------
__global__ void k_aggregate(int L, int N) {
    int gw = (blockIdx.x * blockDim.x + threadIdx.x) >> 5;
    if (gw >= N) return;
    int lane = threadIdx.x & 31;
    int c0 = lane << 1;
    int o0 = g_off[gw], o1 = g_off[gw + 1];
    float aS0 = 0, aS1 = 0, aX0 = 0, aX1 = 0, aY0 = 0, aY1 = 0, aZ0 = 0, aZ1 = 0;
    const __half2* tab = g_wtabh + (size_t)L * NTAB * 320;
    for (int p = o0; p < o1; ++p) {
        float4 rec = g_rec[p];
        float r = rec.w;
        if (r >= RMAXF) continue;  // fc=0 -> all path weights 0
        int src = g_srcs[p];
        float tt = r * ((float)(NTAB - 1) / RMAXF);
        int i0 = (int)tt;
        if (i0 > NTAB - 2) i0 = NTAB - 2;
        float f = tt - (float)i0;
        const __half2* row = tab + (size_t)i0 * 320 + c0;
        uint2 q1 = *(const uint2*)(row);
        uint2 q2 = *(const uint2*)(row + 64);
        uint2 q3 = *(const uint2*)(row + 128);
        uint2 q4 = *(const uint2*)(row + 192);
        uint2 q5 = *(const uint2*)(row + 256);
        float w1a, w1b, w2a, w2b, w3a, w3b, w4a, w4b, w5a, w5b;
        lerp2(q1, f, w1a, w1b);
        lerp2(q2, f, w2a, w2b);
        lerp2(q3, f, w3a, w3b);
        lerp2(q4, f, w4a, w4b);
        lerp2(q5, f, w5a, w5b);

        float2 s01 = *(const float2*)(g_s + src * 64 + c0);
        const float* vp = g_v + src * 192 + c0;
        float2 vx = *(const float2*)(vp);
        float2 vy = *(const float2*)(vp + 64);
        float2 vz = *(const float2*)(vp + 128);
        float yx = rec.x, yy = rec.y, yz = rec.z;

        float vd0 = vx.x * yx + vy.x * yy + vz.x * yz;
        float vd1 = vx.y * yx + vy.y * yy + vz.y * yz;
        aS0 += w1a * s01.x + w2a * vd0;
        aS1 += w1b * s01.y + w2b * vd1;
        float t3a = w3a * s01.x, t3b = w3b * s01.y;
        aX0 += t3a * yx + w4a * vx.x + w5a * (vy.x * yz - vz.x * yy);
        aY0 += t3a * yy + w4a * vy.x + w5a * (vz.x * yx - vx.x * yz);
        aZ0 += t3a * yz + w4a * vz.x + w5a * (vx.x * yy - vy.x * yx);
        aX1 += t3b * yx + w4b * vx.y + w5b * (vy.y * yz - vz.y * yy);
        aY1 += t3b * yy + w4b * vy.y + w5b * (vz.y * yx - vx.y * yz);
        aZ1 += t3b * yz + w4b * vz.y + w5b * (vx.y * yy - vy.y * yx);
    }
    *(float2*)(g_as + gw * 64 + c0) = make_float2(aS0, aS1);
    float* ov = g_av + gw * 192 + c0;
    *(float2*)(ov) = make_float2(aX0, aX1);
    *(float2*)(ov + 64) = make_float2(aY0, aY1);
    *(float2*)(ov + 128) = make_float2(aZ0, aZ1);
}

// ---------------- node self-interaction + resnet ----------------
__global__ void k_node(int L, int N, const float* __restrict__ wss,
                       const float* __restrict__ wsv,
                       const float* __restrict__ wgt) {
    __shared__ float sWs[4096];
    __shared__ float sWv[4096];
    __shared__ float sWg[4096];
    const float* ps = wss + (size_t)L * 4096;
    const float* pv = wsv + (size_t)L * 4096;
    const float* pg = wgt + (size_t)L * 4096;
    for (int i = threadIdx.x; i < 4096; i += blockDim.x) {
        sWs[i] = ps[i]; sWv[i] = pv[i]; sWg[i] = pg[i];
    }
    __syncthreads();
    int gw = blockIdx.x * 8 + (threadIdx.x >> 5);
    if (gw >= N) return;
    int lane = threadIdx.x & 31;
    int c0 = lane << 1;
    float2 a = *(const float2*)(g_as + gw * 64 + c0);
    const float* avp = g_av + gw * 192 + c0;
    float2 ax = *(const float2*)(avp);
    float2 ay = *(const float2*)(avp + 64);
    float2 az = *(const float2*)(avp + 128);
    float gs0 = 0, gs1 = 0, t0 = 0, t1 = 0;
    float vx0 = 0, vx1 = 0, vy0 = 0, vy1 = 0, vz0 = 0, vz1 = 0;
#pragma unroll
    for (int j = 0; j < 64; j++) {
        int sl = j >> 1;
        float aj = __shfl_sync(0xffffffffu, (j & 1) ? a.y : a.x, sl);
        float jx = __shfl_sync(0xffffffffu, (j & 1) ? ax.y : ax.x, sl);
        float jy = __shfl_sync(0xffffffffu, (j & 1) ? ay.y : ay.x, sl);
        float jz = __shfl_sync(0xffffffffu, (j & 1) ? az.y : az.x, sl);
        float2 wg2 = *(const float2*)(sWg + j * 64 + c0);
        float2 ws2 = *(const float2*)(sWs + j * 64 + c0);
        float2 wv2 = *(const float2*)(sWv + j * 64 + c0);
        gs0 += aj * wg2.x; gs1 += aj * wg2.y;
        t0 += aj * ws2.x;  t1 += aj * ws2.y;
        vx0 += jx * wv2.x; vx1 += jx * wv2.y;
        vy0 += jy * wv2.x; vy1 += jy * wv2.y;
        vz0 += jz * wv2.x; vz1 += jz * wv2.y;
    }
    float g0 = 1.f / (1.f + expf(-gs0));
    float g1 = 1.f / (1.f + expf(-gs1));
    float si0 = t0 / (1.f + expf(-t0));
    float si1 = t1 / (1.f + expf(-t1));
    float* sp = g_s + gw * 64 + c0;
    float2 sv = *(float2*)sp;
    sv.x += si0; sv.y += si1;
    *(float2*)sp = sv;
    float* vp = g_v + gw * 192 + c0;
    float2 vv;
    vv = *(float2*)(vp);       vv.x += vx0 * g0; vv.y += vx1 * g1; *(float2*)(vp) = vv;
    vv = *(float2*)(vp + 64);  vv.x += vy0 * g0; vv.y += vy1 * g1; *(float2*)(vp + 64) = vv;
    vv = *(float2*)(vp + 128); vv.x += vz0 * g0; vv.y += vz1 * g1; *(float2*)(vp + 128) = vv;
}

// ---------------- final energy head: (s @ w_lin1) @ w_lin2 ----------------
__global__ void k_energy(int N, const float* __restrict__ wl1,
                         const float* __restrict__ wl2,
                         float* __restrict__ out) {
    __shared__ float sW[1024];
    __shared__ float sw2[16];
    for (int i = threadIdx.x; i < 1024; i += blockDim.x) sW[i] = wl1[i];
    if (threadIdx.x < 16) sw2[threadIdx.x] = wl2[threadIdx.x];
    __syncthreads();
    int gw = blockIdx.x * 8 + (threadIdx.x >> 5);
    if (gw >= N) return;
    int lane = threadIdx.x & 31;
    int c0 = lane << 1;
    float2 s = *(const float2*)(g_s + gw * 64 + c0);
    float p[16];
#pragma unroll
    for (int k = 0; k < 16; k++)
        p[k] = s.x * sW[c0 * 16 + k] + s.y * sW[(c0 + 1) * 16 + k];
#pragma unroll
    for (int d = 16; d >= 1; d >>= 1) {
#pragma unroll
        for (int k = 0; k < 16; k++) p[k] += __shfl_down_sync(0xffffffffu, p[k], d);
    }
    if (lane == 0) {
        float e = 0.f;
#pragma unroll
        for (int k = 0; k < 16; k++) e += p[k] * sw2[k];
        out[gw] = e;
    }
}

// ---------------- launch ----------------
extern "C" void kernel_launch(void* const* d_in, const int* in_sizes, int n_in,
                              void* d_out, int out_size) {
    const int*   atom_type = (const int*)d_in[0];
    const float* atom_pos  = (const float*)d_in[1];
    const int*   edge_src  = (const int*)d_in[2];
    const int*   edge_dst  = (const int*)d_in[3];
    const float* shift     = (const float*)d_in[4];
    const float* cell      = (const float*)d_in[5];
    const int*   image_idx = (const int*)d_in[6];
    const float* w_lin_in  = (const float*)d_in[7];
    const float* mw1       = (const float*)d_in[8];
    const float* mb1       = (const float*)d_in[9];
    const float* mw2       = (const float*)d_in[10];
    const float* wss       = (const float*)d_in[11];
    const float* wsv       = (const float*)d_in[12];
    const float* wgt       = (const float*)d_in[13];
    const float* wl1       = (const float*)d_in[14];
    const float* wl2       = (const float*)d_in[15];
    int N = in_sizes[0];
    int E = in_sizes[2];
    float* out = (float*)d_out;

    k_init<<<(N * 192 + 255) / 256, 256>>>(atom_type, w_lin_in, N);
    k_edge_pre<<<(E + 255) / 256, 256>>>(atom_pos, edge_src, edge_dst, shift,
                                         cell, image_idx, E);
    k_scan<<<1, 1024>>>(N);
    k_scatter<<<(E + 255) / 256, 256>>>(edge_src, edge_dst, E);
    k_table<<<NLAYERS * NTAB, 64>>>(mw1, mb1, mw2);
    k_pack<<<NLAYERS * NTAB, 64>>>();
    for (int L = 0; L < NLAYERS; ++L) {
        k_aggregate<<<(N * 32 + 255) / 256, 256>>>(L, N);
        k_node<<<(N + 7) / 8, 256>>>(L, N, wss, wsv, wgt);
    }
    k_energy<<<(N + 7) / 8, 256>>>(N, wl1, wl2, out);
}

// round 3
// speedup vs baseline: 1.1085x; 1.0667x over previous
#include <cuda_runtime.h>
#include <cuda_fp16.h>
#include <math.h>

#define MAXN 16384
#define MAXE 524288
#define NTAB 4096
#define RMAXF 5.0f
#define NLAYERS 3

// ---------------- static scratch (no allocation allowed) ----------------
__device__ float4  g_ev[MAXE];        // unsorted per-edge {y1.x,y1.y,y1.z,r}
__device__ float4  g_rec[MAXE];       // dst-sorted records
__device__ int     g_srcs[MAXE];      // dst-sorted src index
__device__ int     g_hist[MAXN];
__device__ int     g_cur[MAXN];
__device__ int     g_off[MAXN + 1];
__device__ float   g_h[NLAYERS * NTAB * 64];        // silu hidden activations
__device__ float   g_wtab[NLAYERS * NTAB * 320];    // fp32 staging table
__device__ __half2 g_wtabh[NLAYERS * NTAB * 320];   // packed (val, delta) table
__device__ float   g_s[MAXN * 64];
__device__ float   g_v[MAXN * 192];   // layout [n][3][64]
__device__ float   g_as[MAXN * 64];
__device__ float   g_av[MAXN * 192];
__device__ __half2 g_sh[MAXN * 32];   // half mirror of s, (c0,c0+1) pairs
__device__ __half2 g_vh[MAXN * 96];   // half mirror of v, [n][3][32] half2

// ---------------- init: s = w_lin_in[type], v = 0, hist = 0 ----------------
__global__ void k_init(const int* __restrict__ atom_type,
                       const float* __restrict__ w_lin_in, int N) {
    int i = blockIdx.x * blockDim.x + threadIdx.x;
    if (i < N * 192) g_v[i] = 0.f;
    if (i < N * 96) g_vh[i] = __floats2half2_rn(0.f, 0.f);
    if (i < N * 64) {
        int n = i >> 6, c = i & 63;
        g_s[i] = w_lin_in[atom_type[n] * 64 + c];
    }
    if (i < N * 32) {
        int n = i >> 5, l = i & 31;
        int t = atom_type[n];
        g_sh[i] = __floats2half2_rn(w_lin_in[t * 64 + 2 * l],
                                    w_lin_in[t * 64 + 2 * l + 1]);
    }
    if (i < N) g_hist[i] = 0;
}

// ---------------- edge preprocess: vec, r, y1; histogram dst ----------------
__global__ void k_edge_pre(const float* __restrict__ pos,
                           const int* __restrict__ esrc,
                           const int* __restrict__ edst,
                           const float* __restrict__ shift,
                           const float* __restrict__ cell,
                           const int* __restrict__ img, int E) {
    int e = blockIdx.x * blockDim.x + threadIdx.x;
    if (e >= E) return;
    int s = esrc[e], d = edst[e];
    float vx = pos[d * 3 + 0] - pos[s * 3 + 0];
    float vy = pos[d * 3 + 1] - pos[s * 3 + 1];
    float vz = pos[d * 3 + 2] - pos[s * 3 + 2];
    float s0 = shift[e * 3 + 0], s1 = shift[e * 3 + 1], s2 = shift[e * 3 + 2];
    const float* Cm = cell + img[s] * 9;
    vx += s0 * Cm[0] + s1 * Cm[3] + s2 * Cm[6];
    vy += s0 * Cm[1] + s1 * Cm[4] + s2 * Cm[7];
    vz += s0 * Cm[2] + s1 * Cm[5] + s2 * Cm[8];
    float r = sqrtf(vx * vx + vy * vy + vz * vz);
    float inv = 1.7320508075688772f / fmaxf(r, 1e-9f);  // sqrt3 * unit
    g_ev[e] = make_float4(vx * inv, vy * inv, vz * inv, r);
    atomicAdd(&g_hist[d], 1);
}

// ---------------- single-block exclusive scan of hist ----------------
__global__ void k_scan(int N) {
    __shared__ int sm[1024];
    int tid = threadIdx.x;
    int per = (N + 1023) >> 10;
    int st = tid * per;
    int s = 0;
    for (int i = 0; i < per; i++) { int idx = st + i; if (idx < N) s += g_hist[idx]; }
    sm[tid] = s;
    __syncthreads();
    for (int d = 1; d < 1024; d <<= 1) {
        int v = (tid >= d) ? sm[tid - d] : 0;
        __syncthreads();
        sm[tid] += v;
        __syncthreads();
    }
    int pre = tid ? sm[tid - 1] : 0;
    for (int i = 0; i < per; i++) {
        int idx = st + i;
        if (idx < N) { g_off[idx] = pre; g_cur[idx] = pre; pre += g_hist[idx]; }
    }
    if (tid == 0) g_off[N] = sm[1023];
}

// ---------------- scatter edges into dst-sorted order ----------------
__global__ void k_scatter(const int* __restrict__ esrc,
                          const int* __restrict__ edst, int E) {
    int e = blockIdx.x * blockDim.x + threadIdx.x;
    if (e >= E) return;
    int d = edst[e];
    int p = atomicAdd(&g_cur[d], 1);
    g_rec[p] = g_ev[e];
    g_srcs[p] = esrc[e];
}

// ---------------- stage 1: hidden activations h = silu(emb@W1+b1) ----------------
__global__ void k_table_h(const float* __restrict__ mw1,
                          const float* __restrict__ mb1) {
    int L = blockIdx.x / NTAB;
    int entry = blockIdx.x % NTAB;
    int t = threadIdx.x;  // 0..63
    float r = (float)entry * (RMAXF / (float)(NTAB - 1));
    float rs = fmaxf(r, 1e-9f);
    float x = r / RMAXF;
    float x2 = x * x;
    float x6 = x2 * x2 * x2;
    float fc = 1.f - 28.f * x6 + 48.f * x6 * x - 21.f * x6 * x2;
    if (x >= 1.f) fc = 0.f;
    float cscale = sqrtf(2.f / RMAXF) * fc / rs;
    float arg = 3.14159265358979323846f * rs / RMAXF;
    float emb[8];
#pragma unroll
    for (int n = 0; n < 8; n++) emb[n] = cscale * sinf((float)(n + 1) * arg);

    float h = mb1[L * 64 + t];
#pragma unroll
    for (int j = 0; j < 8; j++) h += emb[j] * mw1[(L * 8 + j) * 64 + t];
    h = h / (1.f + expf(-h));  // silu
    g_h[((size_t)L * NTAB + entry) * 64 + t] = h;
}

// ---------------- stage 2: smem-tiled GEMM  h @ W2 -> table ----------------
// block: 256 threads, 16 entries; thread handles 4 entries x 5 outputs at col c
#define ENT 16
#define JT 16
__global__ void k_table_mm(const float* __restrict__ mw2) {
    __shared__ float sh_h[ENT * 64];       // 4KB
    __shared__ float sh_w[JT * 320];       // 20KB
    int L = blockIdx.y;
    int e_blk = blockIdx.x * ENT;
    int tid = threadIdx.x;
    int c = tid & 63;
    int eg = tid >> 6;  // 0..3  (entry group)
    // load h tile (contiguous)
    const float* hsrc = g_h + ((size_t)L * NTAB + e_blk) * 64;
    for (int i = tid; i < ENT * 64; i += 256) sh_h[i] = hsrc[i];

    float acc[4][5];
#pragma unroll
    for (int q = 0; q < 4; q++)
#pragma unroll
        for (int k = 0; k < 5; k++) acc[q][k] = 0.f;

    for (int j0 = 0; j0 < 64; j0 += JT) {
        __syncthreads();
        const float* wsrc = mw2 + ((size_t)L * 64 + j0) * 320;
        for (int i = tid; i < JT * 320; i += 256) sh_w[i] = wsrc[i];
        __syncthreads();
#pragma unroll
        for (int j = 0; j < JT; j++) {
            float w0 = sh_w[j * 320 + 0 * 64 + c];
            float w1 = sh_w[j * 320 + 1 * 64 + c];
            float w2 = sh_w[j * 320 + 2 * 64 + c];
            float w3 = sh_w[j * 320 + 3 * 64 + c];
            float w4 = sh_w[j * 320 + 4 * 64 + c];
#pragma unroll
            for (int q = 0; q < 4; q++) {
                float hj = sh_h[(eg * 4 + q) * 64 + j0 + j];
                acc[q][0] += hj * w0;
                acc[q][1] += hj * w1;
                acc[q][2] += hj * w2;
                acc[q][3] += hj * w3;
                acc[q][4] += hj * w4;
            }
        }
    }
    const float ISD = 0.17677669529663687f;          // 1/sqrt(32)
    const float SC[5] = {ISD, ISD * 0.57735026918962576f, ISD, ISD,
                         ISD * 0.70710678118654752f};
#pragma unroll
    for (int q = 0; q < 4; q++) {
        int e = e_blk + eg * 4 + q;
        float* out = g_wtab + ((size_t)L * NTAB + e) * 320;
#pragma unroll
        for (int k = 0; k < 5; k++) out[k * 64 + c] = acc[q][k] * SC[k];
    }
}

// ---------------- pack fp32 table into half2 (val, delta) ----------------
__global__ void k_pack() {
    int L = blockIdx.x / NTAB;
    int entry = blockIdx.x % NTAB;
    int t = threadIdx.x;  // 0..63
    const float* cur = g_wtab + ((size_t)L * NTAB + entry) * 320;
    const float* nxt = cur + (entry < NTAB - 1 ? 320 : 0);
    __half2* out = g_wtabh + ((size_t)L * NTAB + entry) * 320;
#pragma unroll
    for (int k = 0; k < 5; k++) {
        float v = cur[k * 64 + t];
        float d = nxt[k * 64 + t] - v;
        out[k * 64 + t] = __floats2half2_rn(v, d);
    }
}

__device__ __forceinline__ void lerp2(uint2 q, float f, float& wa, float& wb) {
    float2 a = __half22float2(*(__half2*)&q.x);  // (val_a, delta_a)
    float2 b = __half22float2(*(__half2*)&q.y);  // (val_b, delta_b)
    wa = fmaf(f, a.y, a.x);
    wb = fmaf(f, b.y, b.x);
}

// ---------------- main per-layer aggregate (warp per dst atom) ----------------
__global__ void k_aggregate(int L, int N) {
    int gw = (blockIdx.x * blockDim.x + threadIdx.x) >> 5;
    if (gw >= N) return;
    int lane = threadIdx.x & 31;
    int c0 = lane << 1;
    int o0 = g_off[gw], o1 = g_off[gw + 1];
    float aS0 = 0, aS1 = 0, aX0 = 0, aX1 = 0, aY0 = 0, aY1 = 0, aZ0 = 0, aZ1 = 0;
    const __half2* tab = g_wtabh + (size_t)L * NTAB * 320;
    for (int p = o0; p < o1; ++p) {
        float4 rec = g_rec[p];
        float r = rec.w;
        if (r >= RMAXF) continue;  // fc=0 -> all path weights 0
        int src = g_srcs[p];
        float tt = r * ((float)(NTAB - 1) / RMAXF);
        int i0 = (int)tt;
        if (i0 > NTAB - 2) i0 = NTAB - 2;
        float f = tt - (float)i0;
        const __half2* row = tab + (size_t)i0 * 320 + c0;
        uint2 q1 = *(const uint2*)(row);
        uint2 q2 = *(const uint2*)(row + 64);
        uint2 q3 = *(const uint2*)(row + 128);
        uint2 q4 = *(const uint2*)(row + 192);
        uint2 q5 = *(const uint2*)(row + 256);
        float w1a, w1b, w2a, w2b, w3a, w3b, w4a, w4b, w5a, w5b;
        lerp2(q1, f, w1a, w1b);
        lerp2(q2, f, w2a, w2b);
        lerp2(q3, f, w3a, w3b);
        lerp2(q4, f, w4a, w4b);
        lerp2(q5, f, w5a, w5b);

        float2 s01 = __half22float2(g_sh[src * 32 + lane]);
        const __half2* vp = g_vh + src * 96 + lane;
        float2 vx = __half22float2(vp[0]);
        float2 vy = __half22float2(vp[32]);
        float2 vz = __half22float2(vp[64]);
        float yx = rec.x, yy = rec.y, yz = rec.z;

        float vd0 = vx.x * yx + vy.x * yy + vz.x * yz;
        float vd1 = vx.y * yx + vy.y * yy + vz.y * yz;
        aS0 += w1a * s01.x + w2a * vd0;
        aS1 += w1b * s01.y + w2b * vd1;
        float t3a = w3a * s01.x, t3b = w3b * s01.y;
        aX0 += t3a * yx + w4a * vx.x + w5a * (vy.x * yz - vz.x * yy);
        aY0 += t3a * yy + w4a * vy.x + w5a * (vz.x * yx - vx.x * yz);
        aZ0 += t3a * yz + w4a * vz.x + w5a * (vx.x * yy - vy.x * yx);
        aX1 += t3b * yx + w4b * vx.y + w5b * (vy.y * yz - vz.y * yy);
        aY1 += t3b * yy + w4b * vy.y + w5b * (vz.y * yx - vx.y * yz);
        aZ1 += t3b * yz + w4b * vz.y + w5b * (vx.y * yy - vy.y * yx);
    }
    *(float2*)(g_as + gw * 64 + c0) = make_float2(aS0, aS1);
    float* ov = g_av + gw * 192 + c0;
    *(float2*)(ov) = make_float2(aX0, aX1);
    *(float2*)(ov + 64) = make_float2(aY0, aY1);
    *(float2*)(ov + 128) = make_float2(aZ0, aZ1);
}

// ---------------- node self-interaction + resnet (+half mirror update) ----------------
__global__ void k_node(int L, int N, const float* __restrict__ wss,
                       const float* __restrict__ wsv,
                       const float* __restrict__ wgt) {
    __shared__ float sWs[4096];
    __shared__ float sWv[4096];
    __shared__ float sWg[4096];
    const float* ps = wss + (size_t)L * 4096;
    const float* pv = wsv + (size_t)L * 4096;
    const float* pg = wgt + (size_t)L * 4096;
    for (int i = threadIdx.x; i < 4096; i += blockDim.x) {
        sWs[i] = ps[i]; sWv[i] = pv[i]; sWg[i] = pg[i];
    }
    __syncthreads();
    int gw = blockIdx.x * 8 + (threadIdx.x >> 5);
    if (gw >= N) return;
    int lane = threadIdx.x & 31;
    int c0 = lane << 1;
    float2 a = *(const float2*)(g_as + gw * 64 + c0);
    const float* avp = g_av + gw * 192 + c0;
    float2 ax = *(const float2*)(avp);
    float2 ay = *(const float2*)(avp + 64);
    float2 az = *(const float2*)(avp + 128);
    float gs0 = 0, gs1 = 0, t0 = 0, t1 = 0;
    float vx0 = 0, vx1 = 0, vy0 = 0, vy1 = 0, vz0 = 0, vz1 = 0;
#pragma unroll
    for (int j = 0; j < 64; j++) {
        int sl = j >> 1;
        float aj = __shfl_sync(0xffffffffu, (j & 1) ? a.y : a.x, sl);
        float jx = __shfl_sync(0xffffffffu, (j & 1) ? ax.y : ax.x, sl);
        float jy = __shfl_sync(0xffffffffu, (j & 1) ? ay.y : ay.x, sl);
        float jz = __shfl_sync(0xffffffffu, (j & 1) ? az.y : az.x, sl);
        float2 wg2 = *(const float2*)(sWg + j * 64 + c0);
        float2 ws2 = *(const float2*)(sWs + j * 64 + c0);
        float2 wv2 = *(const float2*)(sWv + j * 64 + c0);
        gs0 += aj * wg2.x; gs1 += aj * wg2.y;
        t0 += aj * ws2.x;  t1 += aj * ws2.y;
        vx0 += jx * wv2.x; vx1 += jx * wv2.y;
        vy0 += jy * wv2.x; vy1 += jy * wv2.y;
        vz0 += jz * wv2.x; vz1 += jz * wv2.y;
    }
    float g0 = 1.f / (1.f + expf(-gs0));
    float g1 = 1.f / (1.f + expf(-gs1));
    float si0 = t0 / (1.f + expf(-t0));
    float si1 = t1 / (1.f + expf(-t1));
    float* sp = g_s + gw * 64 + c0;
    float2 sv = *(float2*)sp;
    sv.x += si0; sv.y += si1;
    *(float2*)sp = sv;
    g_sh[gw * 32 + lane] = __floats2half2_rn(sv.x, sv.y);
    float* vp = g_v + gw * 192 + c0;
    __half2* vhp = g_vh + gw * 96 + lane;
    float2 vv;
    vv = *(float2*)(vp);       vv.x += vx0 * g0; vv.y += vx1 * g1;
    *(float2*)(vp) = vv;       vhp[0]  = __floats2half2_rn(vv.x, vv.y);
    vv = *(float2*)(vp + 64);  vv.x += vy0 * g0; vv.y += vy1 * g1;
    *(float2*)(vp + 64) = vv;  vhp[32] = __floats2half2_rn(vv.x, vv.y);
    vv = *(float2*)(vp + 128); vv.x += vz0 * g0; vv.y += vz1 * g1;
    *(float2*)(vp + 128) = vv; vhp[64] = __floats2half2_rn(vv.x, vv.y);
}

// ---------------- final energy head: (s @ w_lin1) @ w_lin2 ----------------
__global__ void k_energy(int N, const float* __restrict__ wl1,
                         const float* __restrict__ wl2,
                         float* __restrict__ out) {
    __shared__ float sW[1024];
    __shared__ float sw2[16];
    for (int i = threadIdx.x; i < 1024; i += blockDim.x) sW[i] = wl1[i];
    if (threadIdx.x < 16) sw2[threadIdx.x] = wl2[threadIdx.x];
    __syncthreads();
    int gw = blockIdx.x * 8 + (threadIdx.x >> 5);
    if (gw >= N) return;
    int lane = threadIdx.x & 31;
    int c0 = lane << 1;
    float2 s = *(const float2*)(g_s + gw * 64 + c0);
    float p[16];
#pragma unroll
    for (int k = 0; k < 16; k++)
        p[k] = s.x * sW[c0 * 16 + k] + s.y * sW[(c0 + 1) * 16 + k];
#pragma unroll
    for (int d = 16; d >= 1; d >>= 1) {
#pragma unroll
        for (int k = 0; k < 16; k++) p[k] += __shfl_down_sync(0xffffffffu, p[k], d);
    }
    if (lane == 0) {
        float e = 0.f;
#pragma unroll
        for (int k = 0; k < 16; k++) e += p[k] * sw2[k];
        out[gw] = e;
    }
}

// ---------------- launch ----------------
extern "C" void kernel_launch(void* const* d_in, const int* in_sizes, int n_in,
                              void* d_out, int out_size) {
    const int*   atom_type = (const int*)d_in[0];
    const float* atom_pos  = (const float*)d_in[1];
    const int*   edge_src  = (const int*)d_in[2];
    const int*   edge_dst  = (const int*)d_in[3];
    const float* shift     = (const float*)d_in[4];
    const float* cell      = (const float*)d_in[5];
    const int*   image_idx = (const int*)d_in[6];
    const float* w_lin_in  = (const float*)d_in[7];
    const float* mw1       = (const float*)d_in[8];
    const float* mb1       = (const float*)d_in[9];
    const float* mw2       = (const float*)d_in[10];
    const float* wss       = (const float*)d_in[11];
    const float* wsv       = (const float*)d_in[12];
    const float* wgt       = (const float*)d_in[13];
    const float* wl1       = (const float*)d_in[14];
    const float* wl2       = (const float*)d_in[15];
    int N = in_sizes[0];
    int E = in_sizes[2];
    float* out = (float*)d_out;

    k_init<<<(N * 192 + 255) / 256, 256>>>(atom_type, w_lin_in, N);
    k_edge_pre<<<(E + 255) / 256, 256>>>(atom_pos, edge_src, edge_dst, shift,
                                         cell, image_idx, E);
    k_scan<<<1, 1024>>>(N);
    k_scatter<<<(E + 255) / 256, 256>>>(edge_src, edge_dst, E);
    k_table_h<<<NLAYERS * NTAB, 64>>>(mw1, mb1);
    {
        dim3 g(NTAB / ENT, NLAYERS);
        k_table_mm<<<g, 256>>>(mw2);
    }
    k_pack<<<NLAYERS * NTAB, 64>>>();
    for (int L = 0; L < NLAYERS; ++L) {
        k_aggregate<<<(N * 32 + 255) / 256, 256>>>(L, N);
        k_node<<<(N + 7) / 8, 256>>>(L, N, wss, wsv, wgt);
    }
    k_energy<<<(N + 7) / 8, 256>>>(N, wl1, wl2, out);
}

// round 4
// speedup vs baseline: 1.1909x; 1.0743x over previous
#include <cuda_runtime.h>
#include <cuda_fp16.h>
#include <math.h>

#define MAXN 16384
#define MAXE 524288
#define NTAB 4096
#define RMAXF 5.0f
#define NLAYERS 3

// ---------------- static scratch (no allocation allowed) ----------------
__device__ float4  g_ev[MAXE];        // unsorted per-edge {y1.x,y1.y,y1.z,r}
__device__ float4  g_rec[MAXE];       // dst-sorted records
__device__ int     g_srcs[MAXE];      // dst-sorted src index
__device__ int     g_hist[MAXN];
__device__ int     g_cur[MAXN];
__device__ int     g_off[MAXN + 1];
__device__ float   g_h[NLAYERS * NTAB * 64];        // silu hidden activations
__device__ float   g_wtab[NLAYERS * NTAB * 320];    // fp32 staging table
// packed (val,delta) tables, per-lane contiguous:
__device__ uint4   g_tA[NLAYERS * NTAB * 32];       // paths 1,2 : 16B/lane
__device__ uint4   g_tB[NLAYERS * NTAB * 32];       // paths 3,4 : 16B/lane
__device__ uint2   g_tC[NLAYERS * NTAB * 32];       // path 5    : 8B/lane
__device__ float   g_s[MAXN * 64];
__device__ float   g_v[MAXN * 192];   // layout [n][3][64]
__device__ float   g_as[MAXN * 64];
__device__ float   g_av[MAXN * 192];
__device__ uint4   g_feat[MAXN * 32]; // per lane: {s h2, vx h2, vy h2, vz h2}

// ---------------- init: s = w_lin_in[type], v = 0, hist = 0 ----------------
__global__ void k_init(const int* __restrict__ atom_type,
                       const float* __restrict__ w_lin_in, int N) {
    int i = blockIdx.x * blockDim.x + threadIdx.x;
    if (i < N * 192) g_v[i] = 0.f;
    if (i < N * 64) {
        int n = i >> 6, c = i & 63;
        g_s[i] = w_lin_in[atom_type[n] * 64 + c];
    }
    if (i < N * 32) {
        int n = i >> 5, l = i & 31;
        int t = atom_type[n];
        __half2 s2 = __floats2half2_rn(w_lin_in[t * 64 + 2 * l],
                                       w_lin_in[t * 64 + 2 * l + 1]);
        __half2 z2 = __floats2half2_rn(0.f, 0.f);
        uint4 f4;
        f4.x = *(unsigned*)&s2; f4.y = *(unsigned*)&z2;
        f4.z = *(unsigned*)&z2; f4.w = *(unsigned*)&z2;
        g_feat[i] = f4;
    }
    if (i < N) g_hist[i] = 0;
}

// ---------------- edge preprocess: vec, r, y1; histogram dst ----------------
__global__ void k_edge_pre(const float* __restrict__ pos,
                           const int* __restrict__ esrc,
                           const int* __restrict__ edst,
                           const float* __restrict__ shift,
                           const float* __restrict__ cell,
                           const int* __restrict__ img, int E) {
    int e = blockIdx.x * blockDim.x + threadIdx.x;
    if (e >= E) return;
    int s = esrc[e], d = edst[e];
    float vx = pos[d * 3 + 0] - pos[s * 3 + 0];
    float vy = pos[d * 3 + 1] - pos[s * 3 + 1];
    float vz = pos[d * 3 + 2] - pos[s * 3 + 2];
    float s0 = shift[e * 3 + 0], s1 = shift[e * 3 + 1], s2 = shift[e * 3 + 2];
    const float* Cm = cell + img[s] * 9;
    vx += s0 * Cm[0] + s1 * Cm[3] + s2 * Cm[6];
    vy += s0 * Cm[1] + s1 * Cm[4] + s2 * Cm[7];
    vz += s0 * Cm[2] + s1 * Cm[5] + s2 * Cm[8];
    float r = sqrtf(vx * vx + vy * vy + vz * vz);
    float inv = 1.7320508075688772f / fmaxf(r, 1e-9f);  // sqrt3 * unit
    g_ev[e] = make_float4(vx * inv, vy * inv, vz * inv, r);
    atomicAdd(&g_hist[d], 1);
}

// ---------------- single-block exclusive scan of hist ----------------
__global__ void k_scan(int N) {
    __shared__ int sm[1024];
    int tid = threadIdx.x;
    int per = (N + 1023) >> 10;
    int st = tid * per;
    int s = 0;
    for (int i = 0; i < per; i++) { int idx = st + i; if (idx < N) s += g_hist[idx]; }
    sm[tid] = s;
    __syncthreads();
    for (int d = 1; d < 1024; d <<= 1) {
        int v = (tid >= d) ? sm[tid - d] : 0;
        __syncthreads();
        sm[tid] += v;
        __syncthreads();
    }
    int pre = tid ? sm[tid - 1] : 0;
    for (int i = 0; i < per; i++) {
        int idx = st + i;
        if (idx < N) { g_off[idx] = pre; g_cur[idx] = pre; pre += g_hist[idx]; }
    }
    if (tid == 0) g_off[N] = sm[1023];
}

// ---------------- scatter edges into dst-sorted order ----------------
__global__ void k_scatter(const int* __restrict__ esrc,
                          const int* __restrict__ edst, int E) {
    int e = blockIdx.x * blockDim.x + threadIdx.x;
    if (e >= E) return;
    int d = edst[e];
    int p = atomicAdd(&g_cur[d], 1);
    g_rec[p] = g_ev[e];
    g_srcs[p] = esrc[e];
}

// ---------------- stage 1: hidden activations h = silu(emb@W1+b1) ----------------
__global__ void k_table_h(const float* __restrict__ mw1,
                          const float* __restrict__ mb1) {
    int L = blockIdx.x / NTAB;
    int entry = blockIdx.x % NTAB;
    int t = threadIdx.x;  // 0..63
    float r = (float)entry * (RMAXF / (float)(NTAB - 1));
    float rs = fmaxf(r, 1e-9f);
    float x = r / RMAXF;
    float x2 = x * x;
    float x6 = x2 * x2 * x2;
    float fc = 1.f - 28.f * x6 + 48.f * x6 * x - 21.f * x6 * x2;
    if (x >= 1.f) fc = 0.f;
    float cscale = sqrtf(2.f / RMAXF) * fc / rs;
    float arg = 3.14159265358979323846f * rs / RMAXF;
    float emb[8];
#pragma unroll
    for (int n = 0; n < 8; n++) emb[n] = cscale * sinf((float)(n + 1) * arg);

    float h = mb1[L * 64 + t];
#pragma unroll
    for (int j = 0; j < 8; j++) h += emb[j] * mw1[(L * 8 + j) * 64 + t];
    h = h / (1.f + expf(-h));  // silu
    g_h[((size_t)L * NTAB + entry) * 64 + t] = h;
}

// ---------------- stage 2: smem-tiled GEMM  h @ W2 -> table ----------------
#define ENT 16
#define JT 16
__global__ void k_table_mm(const float* __restrict__ mw2) {
    __shared__ float sh_h[ENT * 64];       // 4KB
    __shared__ float sh_w[JT * 320];       // 20KB
    int L = blockIdx.y;
    int e_blk = blockIdx.x * ENT;
    int tid = threadIdx.x;
    int c = tid & 63;
    int eg = tid >> 6;  // 0..3  (entry group)
    const float* hsrc = g_h + ((size_t)L * NTAB + e_blk) * 64;
    for (int i = tid; i < ENT * 64; i += 256) sh_h[i] = hsrc[i];

    float acc[4][5];
#pragma unroll
    for (int q = 0; q < 4; q++)
#pragma unroll
        for (int k = 0; k < 5; k++) acc[q][k] = 0.f;

    for (int j0 = 0; j0 < 64; j0 += JT) {
        __syncthreads();
        const float* wsrc = mw2 + ((size_t)L * 64 + j0) * 320;
        for (int i = tid; i < JT * 320; i += 256) sh_w[i] = wsrc[i];
        __syncthreads();
#pragma unroll
        for (int j = 0; j < JT; j++) {
            float w0 = sh_w[j * 320 + 0 * 64 + c];
            float w1 = sh_w[j * 320 + 1 * 64 + c];
            float w2 = sh_w[j * 320 + 2 * 64 + c];
            float w3 = sh_w[j * 320 + 3 * 64 + c];
            float w4 = sh_w[j * 320 + 4 * 64 + c];
#pragma unroll
            for (int q = 0; q < 4; q++) {
                float hj = sh_h[(eg * 4 + q) * 64 + j0 + j];
                acc[q][0] += hj * w0;
                acc[q][1] += hj * w1;
                acc[q][2] += hj * w2;
                acc[q][3] += hj * w3;
                acc[q][4] += hj * w4;
            }
        }
    }
    const float ISD = 0.17677669529663687f;          // 1/sqrt(32)
    const float SC[5] = {ISD, ISD * 0.57735026918962576f, ISD, ISD,
                         ISD * 0.70710678118654752f};
#pragma unroll
    for (int q = 0; q < 4; q++) {
        int e = e_blk + eg * 4 + q;
        float* out = g_wtab + ((size_t)L * NTAB + e) * 320;
#pragma unroll
        for (int k = 0; k < 5; k++) out[k * 64 + c] = acc[q][k] * SC[k];
    }
}

// ---------------- pack fp32 table into per-lane (val,delta) half2 groups ----------------
__global__ void k_pack() {
    int L = blockIdx.x / NTAB;
    int entry = blockIdx.x % NTAB;
    int l = threadIdx.x;  // 0..31 lane
    const float* cur = g_wtab + ((size_t)L * NTAB + entry) * 320;
    const float* nxt = cur + (entry < NTAB - 1 ? 320 : 0);
    int c0 = l * 2;
    unsigned pk[5][2];
#pragma unroll
    for (int k = 0; k < 5; k++) {
        float va = cur[k * 64 + c0],     vb = cur[k * 64 + c0 + 1];
        float da = nxt[k * 64 + c0] - va, db = nxt[k * 64 + c0 + 1] - vb;
        __half2 ha = __floats2half2_rn(va, da);
        __half2 hb = __floats2half2_rn(vb, db);
        pk[k][0] = *(unsigned*)&ha;
        pk[k][1] = *(unsigned*)&hb;
    }
    size_t base = ((size_t)L * NTAB + entry) * 32 + l;
    g_tA[base] = make_uint4(pk[0][0], pk[0][1], pk[1][0], pk[1][1]);
    g_tB[base] = make_uint4(pk[2][0], pk[2][1], pk[3][0], pk[3][1]);
    g_tC[base] = make_uint2(pk[4][0], pk[4][1]);
}

__device__ __forceinline__ float lerp1(unsigned q, float f) {
    float2 a = __half22float2(*(__half2*)&q);  // (val, delta)
    return fmaf(f, a.y, a.x);
}

// ---------------- main per-layer aggregate (warp per dst atom) ----------------
__global__ void k_aggregate(int L, int N) {
    int gw = (blockIdx.x * blockDim.x + threadIdx.x) >> 5;
    if (gw >= N) return;
    int lane = threadIdx.x & 31;
    int c0 = lane << 1;
    int o0 = g_off[gw], o1 = g_off[gw + 1];
    float aS0 = 0, aS1 = 0, aX0 = 0, aX1 = 0, aY0 = 0, aY1 = 0, aZ0 = 0, aZ1 = 0;
    const uint4* tA = g_tA + (size_t)L * NTAB * 32 + lane;
    const uint4* tB = g_tB + (size_t)L * NTAB * 32 + lane;
    const uint2* tC = g_tC + (size_t)L * NTAB * 32 + lane;

    // software-pipelined: prefetch next rec/src while processing current
    float4 rec; int src;
    if (o0 < o1) { rec = g_rec[o0]; src = g_srcs[o0]; }
    for (int p = o0; p < o1; ++p) {
        float4 crec = rec; int csrc = src;
        int pn = p + 1;
        if (pn < o1) { rec = g_rec[pn]; src = g_srcs[pn]; }

        float tt = fminf(crec.w * ((float)(NTAB - 1) / RMAXF), (float)(NTAB - 1));
        int i0 = (int)tt;
        if (i0 > NTAB - 2) i0 = NTAB - 2;
        float f = tt - (float)i0;
        int ib = i0 * 32;
        uint4 qa = tA[ib];
        uint4 qb = tB[ib];
        uint2 qc = tC[ib];
        uint4 ft = g_feat[csrc * 32 + lane];

        float w1a = lerp1(qa.x, f), w1b = lerp1(qa.y, f);
        float w2a = lerp1(qa.z, f), w2b = lerp1(qa.w, f);
        float w3a = lerp1(qb.x, f), w3b = lerp1(qb.y, f);
        float w4a = lerp1(qb.z, f), w4b = lerp1(qb.w, f);
        float w5a = lerp1(qc.x, f), w5b = lerp1(qc.y, f);

        float2 s01 = __half22float2(*(__half2*)&ft.x);
        float2 vx  = __half22float2(*(__half2*)&ft.y);
        float2 vy  = __half22float2(*(__half2*)&ft.z);
        float2 vz  = __half22float2(*(__half2*)&ft.w);
        float yx = crec.x, yy = crec.y, yz = crec.z;

        float vd0 = vx.x * yx + vy.x * yy + vz.x * yz;
        float vd1 = vx.y * yx + vy.y * yy + vz.y * yz;
        aS0 += w1a * s01.x + w2a * vd0;
        aS1 += w1b * s01.y + w2b * vd1;
        float t3a = w3a * s01.x, t3b = w3b * s01.y;
        aX0 += t3a * yx + w4a * vx.x + w5a * (vy.x * yz - vz.x * yy);
        aY0 += t3a * yy + w4a * vy.x + w5a * (vz.x * yx - vx.x * yz);
        aZ0 += t3a * yz + w4a * vz.x + w5a * (vx.x * yy - vy.x * yx);
        aX1 += t3b * yx + w4b * vx.y + w5b * (vy.y * yz - vz.y * yy);
        aY1 += t3b * yy + w4b * vy.y + w5b * (vz.y * yx - vx.y * yz);
        aZ1 += t3b * yz + w4b * vz.y + w5b * (vx.y * yy - vy.y * yx);
    }
    *(float2*)(g_as + gw * 64 + c0) = make_float2(aS0, aS1);
    float* ov = g_av + gw * 192 + c0;
    *(float2*)(ov) = make_float2(aX0, aX1);
    *(float2*)(ov + 64) = make_float2(aY0, aY1);
    *(float2*)(ov + 128) = make_float2(aZ0, aZ1);
}

// ---------------- node self-interaction + resnet (+feat mirror update) ----------------
__global__ void k_node(int L, int N, const float* __restrict__ wss,
                       const float* __restrict__ wsv,
                       const float* __restrict__ wgt) {
    __shared__ float sWs[4096];
    __shared__ float sWv[4096];
    __shared__ float sWg[4096];
    const float* ps = wss + (size_t)L * 4096;
    const float* pv = wsv + (size_t)L * 4096;
    const float* pg = wgt + (size_t)L * 4096;
    for (int i = threadIdx.x; i < 4096; i += blockDim.x) {
        sWs[i] = ps[i]; sWv[i] = pv[i]; sWg[i] = pg[i];
    }
    __syncthreads();
    int gw = blockIdx.x * 8 + (threadIdx.x >> 5);
    if (gw >= N) return;
    int lane = threadIdx.x & 31;
    int c0 = lane << 1;
    float2 a = *(const float2*)(g_as + gw * 64 + c0);
    const float* avp = g_av + gw * 192 + c0;
    float2 ax = *(const float2*)(avp);
    float2 ay = *(const float2*)(avp + 64);
    float2 az = *(const float2*)(avp + 128);
    float gs0 = 0, gs1 = 0, t0 = 0, t1 = 0;
    float vx0 = 0, vx1 = 0, vy0 = 0, vy1 = 0, vz0 = 0, vz1 = 0;
#pragma unroll
    for (int j = 0; j < 64; j++) {
        int sl = j >> 1;
        float aj = __shfl_sync(0xffffffffu, (j & 1) ? a.y : a.x, sl);
        float jx = __shfl_sync(0xffffffffu, (j & 1) ? ax.y : ax.x, sl);
        float jy = __shfl_sync(0xffffffffu, (j & 1) ? ay.y : ay.x, sl);
        float jz = __shfl_sync(0xffffffffu, (j & 1) ? az.y : az.x, sl);
        float2 wg2 = *(const float2*)(sWg + j * 64 + c0);
        float2 ws2 = *(const float2*)(sWs + j * 64 + c0);
        float2 wv2 = *(const float2*)(sWv + j * 64 + c0);
        gs0 += aj * wg2.x; gs1 += aj * wg2.y;
        t0 += aj * ws2.x;  t1 += aj * ws2.y;
        vx0 += jx * wv2.x; vx1 += jx * wv2.y;
        vy0 += jy * wv2.x; vy1 += jy * wv2.y;
        vz0 += jz * wv2.x; vz1 += jz * wv2.y;
    }
    float g0 = 1.f / (1.f + expf(-gs0));
    float g1 = 1.f / (1.f + expf(-gs1));
    float si0 = t0 / (1.f + expf(-t0));
    float si1 = t1 / (1.f + expf(-t1));
    float* sp = g_s + gw * 64 + c0;
    float2 sv = *(float2*)sp;
    sv.x += si0; sv.y += si1;
    *(float2*)sp = sv;
    float* vp = g_v + gw * 192 + c0;
    float2 v1, v2, v3;
    v1 = *(float2*)(vp);       v1.x += vx0 * g0; v1.y += vx1 * g1; *(float2*)(vp) = v1;
    v2 = *(float2*)(vp + 64);  v2.x += vy0 * g0; v2.y += vy1 * g1; *(float2*)(vp + 64) = v2;
    v3 = *(float2*)(vp + 128); v3.x += vz0 * g0; v3.y += vz1 * g1; *(float2*)(vp + 128) = v3;
    __half2 hs = __floats2half2_rn(sv.x, sv.y);
    __half2 h1 = __floats2half2_rn(v1.x, v1.y);
    __half2 h2 = __floats2half2_rn(v2.x, v2.y);
    __half2 h3 = __floats2half2_rn(v3.x, v3.y);
    uint4 f4;
    f4.x = *(unsigned*)&hs; f4.y = *(unsigned*)&h1;
    f4.z = *(unsigned*)&h2; f4.w = *(unsigned*)&h3;
    g_feat[gw * 32 + lane] = f4;
}

// ---------------- final energy head: (s @ w_lin1) @ w_lin2 ----------------
__global__ void k_energy(int N, const float* __restrict__ wl1,
                         const float* __restrict__ wl2,
                         float* __restrict__ out) {
    __shared__ float sW[1024];
    __shared__ float sw2[16];
    for (int i = threadIdx.x; i < 1024; i += blockDim.x) sW[i] = wl1[i];
    if (threadIdx.x < 16) sw2[threadIdx.x] = wl2[threadIdx.x];
    __syncthreads();
    int gw = blockIdx.x * 8 + (threadIdx.x >> 5);
    if (gw >= N) return;
    int lane = threadIdx.x & 31;
    int c0 = lane << 1;
    float2 s = *(const float2*)(g_s + gw * 64 + c0);
    float p[16];
#pragma unroll
    for (int k = 0; k < 16; k++)
        p[k] = s.x * sW[c0 * 16 + k] + s.y * sW[(c0 + 1) * 16 + k];
#pragma unroll
    for (int d = 16; d >= 1; d >>= 1) {
#pragma unroll
        for (int k = 0; k < 16; k++) p[k] += __shfl_down_sync(0xffffffffu, p[k], d);
    }
    if (lane == 0) {
        float e = 0.f;
#pragma unroll
        for (int k = 0; k < 16; k++) e += p[k] * sw2[k];
        out[gw] = e;
    }
}

// ---------------- launch ----------------
extern "C" void kernel_launch(void* const* d_in, const int* in_sizes, int n_in,
                              void* d_out, int out_size) {
    const int*   atom_type = (const int*)d_in[0];
    const float* atom_pos  = (const float*)d_in[1];
    const int*   edge_src  = (const int*)d_in[2];
    const int*   edge_dst  = (const int*)d_in[3];
    const float* shift     = (const float*)d_in[4];
    const float* cell      = (const float*)d_in[5];
    const int*   image_idx = (const int*)d_in[6];
    const float* w_lin_in  = (const float*)d_in[7];
    const float* mw1       = (const float*)d_in[8];
    const float* mb1       = (const float*)d_in[9];
    const float* mw2       = (const float*)d_in[10];
    const float* wss       = (const float*)d_in[11];
    const float* wsv       = (const float*)d_in[12];
    const float* wgt       = (const float*)d_in[13];
    const float* wl1       = (const float*)d_in[14];
    const float* wl2       = (const float*)d_in[15];
    int N = in_sizes[0];
    int E = in_sizes[2];
    float* out = (float*)d_out;

    k_init<<<(N * 192 + 255) / 256, 256>>>(atom_type, w_lin_in, N);
    k_edge_pre<<<(E + 255) / 256, 256>>>(atom_pos, edge_src, edge_dst, shift,
                                         cell, image_idx, E);
    k_scan<<<1, 1024>>>(N);
    k_scatter<<<(E + 255) / 256, 256>>>(edge_src, edge_dst, E);
    k_table_h<<<NLAYERS * NTAB, 64>>>(mw1, mb1);
    {
        dim3 g(NTAB / ENT, NLAYERS);
        k_table_mm<<<g, 256>>>(mw2);
    }
    k_pack<<<NLAYERS * NTAB, 32>>>();
    for (int L = 0; L < NLAYERS; ++L) {
        k_aggregate<<<(N * 32 + 255) / 256, 256>>>(L, N);
        k_node<<<(N + 7) / 8, 256>>>(L, N, wss, wsv, wgt);
    }
    k_energy<<<(N + 7) / 8, 256>>>(N, wl1, wl2, out);
}